// round 5
// baseline (speedup 1.0000x reference)
#include <cuda_runtime.h>
#include <cstdint>
#include <cstddef>

// Bihomogeneous_k3 — warp-per-row, fused re+im, table-free, a-operand
// recomputed from registers (compile-time candidate monomials + select)
// instead of loaded from smem. Removes the per-group a-LDS wavefront.

#define NVAR 5
#define NM 35
#define NPAIR 630
#define NCOL 1225
#define WPB 8
#define NGRP 20

__host__ __device__ constexpr int off_of(int p) { return p * (71 - p) / 2; }
__host__ __device__ constexpr int p_of(int s) {
    int p = 0;
    while (off_of(p + 1) <= s) p++;
    return p;
}

struct IJK { int i, j, k; };
__host__ __device__ constexpr IJK ijk_of(int m) {
    int idx = 0;
    for (int i = 0; i < NVAR; i++)
        for (int j = i; j < NVAR; j++)
            for (int k = j; k < NVAR; k++) {
                if (idx == m) return IJK{i, j, k};
                idx++;
            }
    return IJK{0, 0, 0};
}

template<int... I> struct iseq {};
template<int N, int... I> struct make_iseq : make_iseq<N - 1, N - 1, I...> {};
template<int... I> struct make_iseq<0, I...> { using type = iseq<I...>; };

// monomial zz_P from register-resident z (compile-time indices -> pure FFMA)
template<int P>
__device__ __forceinline__ float2 mono_reg(const float (&zr)[NVAR], const float (&zi)[NVAR]) {
    constexpr IJK t = ijk_of(P);
    const float tr = zr[t.i] * zr[t.j] - zi[t.i] * zi[t.j];
    const float ti = zr[t.i] * zi[t.j] + zi[t.i] * zr[t.j];
    return make_float2(tr * zr[t.k] - ti * zi[t.k], tr * zi[t.k] + ti * zr[t.k]);
}

// select a = zz_p, qoff = p - off(p), p  across candidates [PMIN..PMIN+NJ]
template<int PMIN, int... J>
__device__ __forceinline__ void pick_a(iseq<J...>, int s,
                                       const float (&zr)[NVAR], const float (&zi)[NVAR],
                                       float& ax, float& ay, int& qoff, int& p) {
    {   const float2 m = mono_reg<PMIN>(zr, zi);
        ax = m.x; ay = m.y; qoff = PMIN - off_of(PMIN); p = PMIN; }
    ([&] {
        constexpr int P = PMIN + 1 + J;
        const bool pr = s >= off_of(P);
        const float2 m = mono_reg<P>(zr, zi);
        ax = pr ? m.x : ax;
        ay = pr ? m.y : ay;
        qoff = pr ? (P - off_of(P)) : qoff;
        p = pr ? P : p;
    }(), ...);
}

template<int G>
__device__ __forceinline__ void do_group(const float (&zr)[NVAR], const float (&zi)[NVAR],
                                         const float2* __restrict__ zz,
                                         float* __restrict__ orow,
                                         float* __restrict__ orowi, int lane) {
    const int s = 32 * G + lane;
    if constexpr (32 * G + 31 >= NPAIR) {
        if (s >= NPAIR) return;           // last (partial) group only
    }
    constexpr int pmin = p_of(32 * G);
    constexpr int smax = (32 * G + 31 < NPAIR - 1) ? 32 * G + 31 : NPAIR - 1;
    constexpr int pmax = p_of(smax);

    float ax, ay; int qoff, p;
    pick_a<pmin>(typename make_iseq<pmax - pmin>::type{}, s, zr, zi, ax, ay, qoff, p);

    const int q = s + qoff;
    const float2 b = zz[q];                        // consecutive q: 2 wf / group
    __stcs(orow + s, ax * b.x + ay * b.y);         // re(zz_p * conj(zz_q))
    if (q > p)                                     // strict pair -> im column
        __stcs(orowi + (s - p), ay * b.x - ax * b.y);
}

template<int... G>
__device__ __forceinline__ void all_groups(iseq<G...>,
                                           const float (&zr)[NVAR], const float (&zi)[NVAR],
                                           const float2* __restrict__ zz,
                                           float* __restrict__ orow,
                                           float* __restrict__ orowi, int lane) {
    (do_group<G>(zr, zi, zz, orow, orowi, lane), ...);
}

// monomial index table for stage 1 (smem-based, 2 warp-iters, negligible)
struct TabM { ushort ijk[40]; };
static constexpr TabM make_tabm() {
    TabM t{};
    int m = 0;
    for (int i = 0; i < NVAR; i++)
        for (int j = i; j < NVAR; j++)
            for (int k = j; k < NVAR; k++) {
                t.ijk[m] = (ushort)(i | (j << 4) | (k << 8));
                m++;
            }
    return t;
}
__device__ const TabM g_tabm = make_tabm();

__global__ void __launch_bounds__(WPB * 32)
bihom_k3_kernel(const float* __restrict__ z_re,
                const float* __restrict__ z_im,
                float* __restrict__ out, int B)
{
    const int warp = threadIdx.x >> 5;
    const int lane = threadIdx.x & 31;
    const int row  = blockIdx.x * WPB + warp;

    __shared__ float2 szz[WPB][NM + 1];
    __shared__ __align__(16) float sz[WPB][12];   // [0..4]=re, [5..9]=im, 48B/warp

    if (row >= B) return;   // one row per warp: uniform exit

    // stage 0: row inputs into smem
    if (lane < NVAR)
        sz[warp][lane] = z_re[row * NVAR + lane];
    else if (lane < 2 * NVAR)
        sz[warp][lane] = z_im[row * NVAR + (lane - NVAR)];
    __syncwarp();

    // broadcast z into registers: 3 wide broadcast LDS (float4,float4,float2)
    float zr[NVAR], zi[NVAR];
    {
        const float4 f0 = *reinterpret_cast<const float4*>(&sz[warp][0]);
        const float4 f1 = *reinterpret_cast<const float4*>(&sz[warp][4]);
        const float2 f2 = *reinterpret_cast<const float2*>(&sz[warp][8]);
        zr[0] = f0.x; zr[1] = f0.y; zr[2] = f0.z; zr[3] = f0.w; zr[4] = f1.x;
        zi[0] = f1.y; zi[1] = f1.z; zi[2] = f1.w; zi[3] = f2.x; zi[4] = f2.y;
    }

    // stage 1: 35 complex monomials into smem (b-operand source)
    for (int mm = lane; mm < NM; mm += 32) {
        const unsigned v = g_tabm.ijk[mm];
        const int i = v & 15, j = (v >> 4) & 15, k = (v >> 8) & 15;
        const float ar = sz[warp][i],        ai = sz[warp][NVAR + i];
        const float br = sz[warp][j],        bi = sz[warp][NVAR + j];
        const float cr = sz[warp][k],        ci = sz[warp][NVAR + k];
        const float tr = ar * br - ai * bi;
        const float ti = ar * bi + ai * br;
        szz[warp][mm] = make_float2(tr * cr - ti * ci, tr * ci + ti * cr);
    }
    __syncwarp();

    // stage 2: 630 fused pair-products -> 1225 streaming stores
    float* __restrict__ orow  = out + (size_t)row * NCOL;
    float* __restrict__ orowi = orow + (NPAIR - 1);   // im col = 629 + s - p
    all_groups(typename make_iseq<NGRP>::type{}, zr, zi, szz[warp], orow, orowi, lane);
}

extern "C" void kernel_launch(void* const* d_in, const int* in_sizes, int n_in,
                              void* d_out, int out_size) {
    const float* z_re = (const float*)d_in[0];
    const float* z_im = (const float*)d_in[1];
    float* out = (float*)d_out;
    const int B = in_sizes[0] / NVAR;
    const int grid = (B + WPB - 1) / WPB;
    bihom_k3_kernel<<<grid, WPB * 32>>>(z_re, z_im, out, B);
}

// round 6
// speedup vs baseline: 1.1849x; 1.1849x over previous
#include <cuda_runtime.h>
#include <cstdint>
#include <cstddef>

// Bihomogeneous_k3 — warp-per-row, fused re+im, table-free indexing,
// phase-shifted schedule so main-loop re-stores hit 128B-aligned lines.

#define NVAR 5
#define NM 35
#define NPAIR 630
#define NCOL 1225
#define WPB 8
#define NGRP 20

__host__ __device__ constexpr int off_of(int p) { return p * (71 - p) / 2; }
__host__ __device__ constexpr int p_of(int s) {
    int p = 0;
    while (off_of(p + 1) <= s) p++;
    return p;
}

template<int... I> struct iseq {};
template<int N, int... I> struct make_iseq : make_iseq<N - 1, N - 1, I...> {};
template<int... I> struct make_iseq<0, I...> { using type = iseq<I...>; };

// p for pair index s: pmin + count of compile-time breakpoints passed
template<int PMIN, int... J>
__device__ __forceinline__ int p_from_s(int s, iseq<J...>) {
    int p = PMIN;
    ((p += (s >= off_of(PMIN + 1 + J)) ? 1 : 0), ...);
    return p;
}

template<int G>
__device__ __forceinline__ void do_group(const float2* __restrict__ zz,
                                         float* __restrict__ orow,
                                         float* __restrict__ orowi,
                                         int c0, int lane) {
    const int s = c0 + 32 * G + lane;          // c0 in [0,31]: aligned schedule
    constexpr int smax_static = 32 * G + 62;   // max possible s in this group
    if constexpr (smax_static >= NPAIR) {
        if (s >= NPAIR) return;
    }
    constexpr int pmin = p_of(32 * G);
    constexpr int pmax = p_of(smax_static < NPAIR - 1 ? smax_static : NPAIR - 1);

    const int p = p_from_s<pmin>(s, typename make_iseq<pmax - pmin>::type{});
    const int q = s + p - ((p * (71 - p)) >> 1);   // s - off(p) + p

    const float2 a = zz[p];                        // broadcast: 1 wf
    const float2 b = zz[q];                        // consecutive q: 2 wf
    __stcs(orow + s, a.x * b.x + a.y * b.y);       // ALIGNED 128B store: 1 wf
    if (q > p)                                     // strict pair -> im column
        __stcs(orowi + (s - p), a.y * b.x - a.x * b.y);
}

template<int... G>
__device__ __forceinline__ void all_groups(iseq<G...>, const float2* __restrict__ zz,
                                           float* __restrict__ orow,
                                           float* __restrict__ orowi, int c0, int lane) {
    (do_group<G>(zz, orow, orowi, c0, lane), ...);
}

// monomial index table for stage 1 (2 warp-iterations, negligible traffic)
struct TabM { ushort ijk[40]; };
static constexpr TabM make_tabm() {
    TabM t{};
    int m = 0;
    for (int i = 0; i < NVAR; i++)
        for (int j = i; j < NVAR; j++)
            for (int k = j; k < NVAR; k++) {
                t.ijk[m] = (ushort)(i | (j << 4) | (k << 8));
                m++;
            }
    return t;
}
__device__ const TabM g_tabm = make_tabm();

__global__ void __launch_bounds__(WPB * 32)
bihom_k3_kernel(const float* __restrict__ z_re,
                const float* __restrict__ z_im,
                float* __restrict__ out, int B)
{
    const int warp = threadIdx.x >> 5;
    const int lane = threadIdx.x & 31;
    const int row  = blockIdx.x * WPB + warp;

    __shared__ float2 szz[WPB][NM + 1];
    __shared__ float  sz[WPB][2][NVAR + 3];

    if (row >= B) return;   // one row per warp: uniform exit

    // stage 0: row inputs into smem
    if (lane < NVAR) {
        sz[warp][0][lane] = z_re[row * NVAR + lane];
        sz[warp][1][lane] = z_im[row * NVAR + lane];
    }
    __syncwarp();

    // stage 1: 35 complex monomials z_i z_j z_k
    for (int mm = lane; mm < NM; mm += 32) {
        const unsigned v = g_tabm.ijk[mm];
        const int i = v & 15, j = (v >> 4) & 15, k = (v >> 8) & 15;
        const float ar = sz[warp][0][i], ai = sz[warp][1][i];
        const float br = sz[warp][0][j], bi = sz[warp][1][j];
        const float cr = sz[warp][0][k], ci = sz[warp][1][k];
        const float tr = ar * br - ai * bi;
        const float ti = ar * bi + ai * br;
        szz[warp][mm] = make_float2(tr * cr - ti * ci, tr * ci + ti * cr);
    }
    __syncwarp();

    // stage 2: phase so that (row*NCOL + c0) is 128B-aligned
    const int rowoff = row * NCOL;
    const int c0 = (-rowoff) & 31;

    float* __restrict__ orow  = out + (size_t)rowoff;
    float* __restrict__ orowi = orow + (NPAIR - 1);   // im col = 629 + s - p
    const float2* zz = szz[warp];

    // prologue: columns [0, c0). Here s < 31 < off(1)=35 -> p = 0, q = s.
    {
        const int s0 = c0 - 32 + lane;
        if (s0 >= 0) {
            const float2 a = zz[0];
            const float2 b = zz[s0];
            __stcs(orow + s0, a.x * b.x + a.y * b.y);
            if (s0 > 0)
                __stcs(orowi + s0, a.y * b.x - a.x * b.y);
        }
    }

    all_groups(typename make_iseq<NGRP>::type{}, zz, orow, orowi, c0, lane);
}

extern "C" void kernel_launch(void* const* d_in, const int* in_sizes, int n_in,
                              void* d_out, int out_size) {
    const float* z_re = (const float*)d_in[0];
    const float* z_im = (const float*)d_in[1];
    float* out = (float*)d_out;
    const int B = in_sizes[0] / NVAR;
    const int grid = (B + WPB - 1) / WPB;
    bihom_k3_kernel<<<grid, WPB * 32>>>(z_re, z_im, out, B);
}